// round 9
// baseline (speedup 1.0000x reference)
#include <cuda_runtime.h>
#include <math.h>

// Fused RoPE, positions == arange(S) (reference overwrites token_positions).
//   out[b,s,2k]   = cos(s*w_k)*x[b,s,2k] - sin(s*w_k)*x[b,s,2k+1]
//   out[b,s,2k+1] = sin(s*w_k)*x[b,s,2k] + cos(s*w_k)*x[b,s,2k+1]
//   w_k = 10000^(-k/64) = exp2(-k*log2(10000)/64)
//
// R5-R8 sweep: MLP4@256thr=17.6us, MLP8@256thr=18.4, MLP8@128thr=18.2,
// forced-32reg=22.8. Binding resource = resident warps x front-batched MLP.
// Final probe: R5's 38-reg MLP=4 body at 128-thread blocks ->
// 13 CTAs/SM = 52 warps (81% occ) x MLP4 = highest warps*MLP yet,
// 8192-CTA grid with near-perfect wave balance.

#define BATCH   32
#define SEQ     4096
#define DK      128
#define QUADS   (DK / 4)            // 32 float4 per row
#define COLS    (SEQ * QUADS)       // 131072 (s,q) columns
#define BGROUP  4                   // batches per thread
#define NGROUPS (BATCH / BGROUP)    // 8
#define TPB     128

__global__ void __launch_bounds__(TPB) rope_fused(
        const float4* __restrict__ x, float4* __restrict__ out) {
    int idx = blockIdx.x * blockDim.x + threadIdx.x;   // 0 .. COLS*NGROUPS-1
    int col = idx & (COLS - 1);      // s*QUADS + q
    int g   = idx >> 17;             // batch group 0..7
    int q = col & (QUADS - 1);
    int s = col >> 5;

    const float4* xp = x   + (size_t)col + (size_t)g * (BGROUP * COLS);
    float4*       op = out + (size_t)col + (size_t)g * (BGROUP * COLS);

    // Front-batch all 4 loads (imm offsets): MLP=4, trig hides under latency.
    float4 v0 = xp[0];
    float4 v1 = xp[COLS];
    float4 v2 = xp[2 * COLS];
    float4 v3 = xp[3 * COLS];

    // -log2(10000)/64
    const float C = -0.2076205059304601f;
    float a0 = (float)s * exp2f((float)(2 * q)     * C);
    float a1 = (float)s * exp2f((float)(2 * q + 1) * C);

    float s0, c0, s1, c1;
    sincosf(a0, &s0, &c0);
    sincosf(a1, &s1, &c1);

    float4 r;
#define ROT_STORE(V, OFF)                      \
    r.x = c0 * (V).x - s0 * (V).y;             \
    r.y = s0 * (V).x + c0 * (V).y;             \
    r.z = c1 * (V).z - s1 * (V).w;             \
    r.w = s1 * (V).z + c1 * (V).w;             \
    __stcs(op + (OFF), r)

    ROT_STORE(v0, 0);
    ROT_STORE(v1, COLS);
    ROT_STORE(v2, 2 * COLS);
    ROT_STORE(v3, 3 * COLS);
#undef ROT_STORE
}

extern "C" void kernel_launch(void* const* d_in, const int* in_sizes, int n_in,
                              void* d_out, int out_size) {
    const float* x = (const float*)d_in[0];
    // d_in[1] = token_positions (unused: reference overwrites with arange)
    // d_in[2] = rot (unused: trig recomputed on device)

    int total = COLS * NGROUPS;                  // 1,048,576 threads
    rope_fused<<<total / TPB, TPB>>>((const float4*)x, (float4*)d_out);
}